// round 11
// baseline (speedup 1.0000x reference)
#include <cuda_runtime.h>

#define N_NODESC 50000
#define N_EDGESC 800000
#define E2C (N_EDGESC + N_NODESC)
#define D_INC 128
#define D_HIDC 64
#define D_OUTC 32

// ---------------- scratch (device globals; never referenced from host) --------
__device__ __align__(16) int   g_count[N_NODESC];
__device__ __align__(16) float g_attr_sum[N_NODESC];
__device__ __align__(16) float g_loop_attr[N_NODESC];
__device__ __align__(16) int   g_row_ptr[N_NODESC + 1];
__device__ __align__(16) int   g_cursor[N_NODESC];
__device__ __align__(16) int2  g_csr[E2C];                 // (src, attr-bits)
__device__ __align__(16) float g_xl [N_NODESC * D_HIDC];
__device__ __align__(16) float g_xr [N_NODESC * D_HIDC];
__device__ __align__(16) float g_h  [N_NODESC * D_HIDC];
__device__ __align__(16) float g_xl2[N_NODESC * D_OUTC];
__device__ __align__(16) float g_xr2[N_NODESC * D_OUTC];

__device__ __forceinline__ const float* lin_in_ptr(const float* xparam, int sel) {
    return (sel == 0) ? xparam : g_h;
}

// ---------------- preprocessing ------------------------------------------------
__global__ void init_kernel() {
    int i = blockIdx.x * blockDim.x + threadIdx.x;
    if (i < N_NODESC) {
        g_count[i] = 0;
        g_attr_sum[i] = 0.f;
        g_cursor[i] = 0;
    }
}

__global__ void count_kernel(const int* __restrict__ ei,
                             const float* __restrict__ ew) {
    int e = blockIdx.x * blockDim.x + threadIdx.x;
    if (e < N_EDGESC) {
        int d = ei[N_EDGESC + e];
        if ((unsigned)d < (unsigned)N_NODESC) {
            atomicAdd(&g_count[d], 1);
            atomicAdd(&g_attr_sum[d], ew[e]);
        }
    }
}

// single-block shuffle-based exclusive scan of (count[i]+1) -> row_ptr + loop_attr
__global__ void __launch_bounds__(1024) scan_kernel() {
    __shared__ int wsum[32];
    const int CH = (N_NODESC + 1023) / 1024;   // 49
    int t    = threadIdx.x;
    int lane = t & 31;
    int wid  = t >> 5;
    int beg = t * CH; if (beg > N_NODESC) beg = N_NODESC;
    int end = beg + CH; if (end > N_NODESC) end = N_NODESC;
    int s = 0;
    for (int i = beg; i < end; i++) {
        int c = g_count[i];
        s += c + 1;
        g_loop_attr[i] = g_attr_sum[i] / fmaxf((float)c, 1.0f);
    }
    int val = s;
#pragma unroll
    for (int o = 1; o < 32; o <<= 1) {
        int u = __shfl_up_sync(0xffffffffu, val, o);
        if (lane >= o) val += u;
    }
    if (lane == 31) wsum[wid] = val;
    __syncthreads();
    if (wid == 0) {
        int w = wsum[lane];
#pragma unroll
        for (int o = 1; o < 32; o <<= 1) {
            int u = __shfl_up_sync(0xffffffffu, w, o);
            if (lane >= o) w += u;
        }
        wsum[lane] = w;
    }
    __syncthreads();
    int run = val - s + (wid ? wsum[wid - 1] : 0);
    for (int i = beg; i < end; i++) {
        g_row_ptr[i] = run;
        run += g_count[i] + 1;
    }
    if (t == 0) g_row_ptr[N_NODESC] = E2C;
}

__global__ void scatter_kernel(const int* __restrict__ ei,
                               const float* __restrict__ ew) {
    int e = blockIdx.x * blockDim.x + threadIdx.x;
    if (e < N_EDGESC) {
        int d = ei[N_EDGESC + e];
        int s = ei[e];
        if ((unsigned)d < (unsigned)N_NODESC && (unsigned)s < (unsigned)N_NODESC) {
            int pos = g_row_ptr[d] + atomicAdd(&g_cursor[d], 1);
            g_csr[pos] = make_int2(s, __float_as_int(ew[e]));
        }
    } else if (e < E2C) {
        int v = e - N_EDGESC;
        int pos = g_row_ptr[v] + atomicAdd(&g_cursor[v], 1);
        g_csr[pos] = make_int2(v, __float_as_int(g_loop_attr[v]));
    }
}

// ---------------- split-role linear: role 0 -> yl, role 1 -> yr ------------------
// R10 profile: regs=75 capped occupancy at 32.8% (issue 55.6%). Splitting the
// l/r pair into two role blocks (blockIdx parity) halves accumulator registers
// (single acc[4][4]) with a UNIFORM resource shape, raising occupancy; per
// k-iter 5 LDS issue-slots feed 16 FMAs -> FMA-issue bound. x tile is staged
// twice (once per role) — cheap, x streams through L2.
template <int DI, int DO, int TN, int KC, int PAIR>
__global__ void __launch_bounds__(256) linear_split_kernel(
    const float* __restrict__ xparam,
    const float* __restrict__ Wl, const float* __restrict__ bl,
    const float* __restrict__ Wr, const float* __restrict__ br,
    int insel) {
    constexpr int WS   = DO + 4;
    constexpr int XS   = TN + 1;
    constexpr int NT_H = DO / 4;
    constexpr int NT_N = 256 / NT_H;
    constexpr int R_N  = TN / NT_N;
    static_assert(DI % KC == 0 && R_N == 4, "tile config");
    __shared__ __align__(16) float Ws[KC * WS];
    __shared__ __align__(16) float xs[KC * XS];
    const float* __restrict__ x = lin_in_ptr(xparam, insel);
    int role = blockIdx.x & 1;
    int tile = blockIdx.x >> 1;
    const float* __restrict__ W = role ? Wr : Wl;
    const float* __restrict__ b = role ? br : bl;
    float* __restrict__ y = PAIR ? (role ? g_xr2 : g_xl2)
                                 : (role ? g_xr  : g_xl);
    int t = threadIdx.x;
    int node0 = tile * TN;
    int h0 = (t % NT_H) * 4;
    int n0 = (t / NT_H) * R_N;
    float acc[R_N][4];
#pragma unroll
    for (int r = 0; r < R_N; r++)
#pragma unroll
        for (int c = 0; c < 4; c++) acc[r][c] = 0.f;

    for (int c = 0; c < DI / KC; c++) {
        if (c) __syncthreads();
        for (int i = t; i < DO * KC; i += 256) {
            int r = i / KC, k = i % KC;
            Ws[k * WS + r] = W[r * DI + c * KC + k];
        }
        for (int i = t; i < TN * KC; i += 256) {
            int n = i / KC, k = i % KC;
            int nd = node0 + n;
            xs[k * XS + n] = (nd < N_NODESC) ? x[nd * DI + c * KC + k] : 0.f;
        }
        __syncthreads();
#pragma unroll 4
        for (int k = 0; k < KC; k++) {
            float4 w4 = *reinterpret_cast<const float4*>(&Ws[k * WS + h0]);
            float xvr[R_N];
#pragma unroll
            for (int r = 0; r < R_N; r++) xvr[r] = xs[k * XS + n0 + r];
#pragma unroll
            for (int r = 0; r < R_N; r++) {
                acc[r][0] = fmaf(xvr[r], w4.x, acc[r][0]);
                acc[r][1] = fmaf(xvr[r], w4.y, acc[r][1]);
                acc[r][2] = fmaf(xvr[r], w4.z, acc[r][2]);
                acc[r][3] = fmaf(xvr[r], w4.w, acc[r][3]);
            }
        }
    }
#pragma unroll
    for (int r = 0; r < R_N; r++) {
        int node = node0 + n0 + r;
        if (node < N_NODESC) {
            float4 o;
            o.x = acc[r][0] + b[h0 + 0];
            o.y = acc[r][1] + b[h0 + 1];
            o.z = acc[r][2] + b[h0 + 2];
            o.w = acc[r][3] + b[h0 + 3];
            *reinterpret_cast<float4*>(&y[node * DO + h0]) = o;
        }
    }
}

// ---------------- GATv2 node kernel: warp per node, SINGLE PASS -----------------
// Byte-identical to the R5 champion form (no extra work folded in).
template <int DH, int LAYER>
__global__ void __launch_bounds__(256) gat_node_kernel(
    const float* __restrict__ We, const float* __restrict__ att,
    const float* __restrict__ bias, float* __restrict__ outp) {
    constexpr int PER = DH / 32;
    const float* __restrict__ xl = (LAYER == 0) ? g_xl : g_xl2;
    const float* __restrict__ xr = (LAYER == 0) ? g_xr : g_xr2;
    float* __restrict__ out = (LAYER == 0) ? g_h : outp;
    int v    = (blockIdx.x * blockDim.x + threadIdx.x) >> 5;
    int lane = threadIdx.x & 31;
    if (v >= N_NODESC) return;

    float xrv[PER], wev[PER], attv[PER], bv[PER];
#pragma unroll
    for (int p = 0; p < PER; p++) {
        int h = lane * PER + p;
        xrv[p]  = xr[v * DH + h];
        wev[p]  = We[h];
        attv[p] = att[h];
        bv[p]   = bias[h];
    }
    int beg = g_row_ptr[v], end = g_row_ptr[v + 1];

    float ssum = 0.f;
    float acc[PER];
#pragma unroll
    for (int p = 0; p < PER; p++) acc[p] = 0.f;

    // software pipeline: edge record + x row prefetched one iteration ahead
    int2 ecur = g_csr[beg];
    float xnext[PER];
    {
        const float* b0 = xl + (size_t)ecur.x * DH + lane * PER;
        if (PER == 2) { float2 t2 = *reinterpret_cast<const float2*>(b0); xnext[0] = t2.x; xnext[1] = t2.y; }
        else          { xnext[0] = *b0; }
    }
    for (int idx = beg; idx < end; idx++) {
        float xls[PER];
#pragma unroll
        for (int p = 0; p < PER; p++) xls[p] = xnext[p];
        float a = __int_as_float(ecur.y);
        int2 enext = (idx + 1 < end) ? g_csr[idx + 1] : ecur;
        const float* bn = xl + (size_t)enext.x * DH + lane * PER;
        if (PER == 2) { float2 t2 = *reinterpret_cast<const float2*>(bn); xnext[0] = t2.x; xnext[1] = t2.y; }
        else          { xnext[0] = *bn; }
        ecur = enext;

        float sc = 0.f;
#pragma unroll
        for (int p = 0; p < PER; p++) {
            float m = xls[p] + xrv[p] + a * wev[p];
            m = m > 0.f ? m : 0.2f * m;
            sc = fmaf(attv[p], m, sc);
        }
#pragma unroll
        for (int o = 16; o; o >>= 1) sc += __shfl_xor_sync(0xffffffffu, sc, o);
        float e = __expf(sc);
        ssum += e;
#pragma unroll
        for (int p = 0; p < PER; p++) acc[p] = fmaf(e, xls[p], acc[p]);
    }
    float inv = 1.f / ssum;
#pragma unroll
    for (int p = 0; p < PER; p++) {
        float o = fmaf(acc[p], inv, bv[p]);
        if (LAYER == 0) {
            o = o > 0.f ? o : (__expf(o) - 1.f);            // elu
        } else {
            o = (o > 20.f ? o : log1pf(__expf(o))) + 1e-4f; // softplus + eps
        }
        out[v * DH + lane * PER + p] = o;
    }
}

// ---------------- launch --------------------------------------------------------
extern "C" void kernel_launch(void* const* d_in, const int* in_sizes, int n_in,
                              void* d_out, int out_size) {
    const float* x     = (const float*)d_in[0];
    const int*   ei    = (const int*)d_in[1];      // edge_index: int32
    const float* ew    = (const float*)d_in[2];
    const float* Wl1   = (const float*)d_in[3];
    const float* bl1   = (const float*)d_in[4];
    const float* Wr1   = (const float*)d_in[5];
    const float* br1   = (const float*)d_in[6];
    const float* We1   = (const float*)d_in[7];
    const float* att1  = (const float*)d_in[8];
    const float* bias1 = (const float*)d_in[9];
    const float* Wl2   = (const float*)d_in[10];
    const float* bl2   = (const float*)d_in[11];
    const float* Wr2   = (const float*)d_in[12];
    const float* br2   = (const float*)d_in[13];
    const float* We2   = (const float*)d_in[14];
    const float* att2  = (const float*)d_in[15];
    const float* bias2 = (const float*)d_in[16];
    float*       out   = (float*)d_out;

    // ---- graph preprocessing / CSR (shared by both layers) ----
    init_kernel<<<(N_NODESC + 255) / 256, 256>>>();
    count_kernel<<<(N_EDGESC + 255) / 256, 256>>>(ei, ew);
    scan_kernel<<<1, 1024>>>();
    scatter_kernel<<<(E2C + 255) / 256, 256>>>(ei, ew);

    const int GRID_GAT  = (N_NODESC * 32 + 255) / 256;     // warp per node
    const int NB_L1     = (N_NODESC + 63) / 64;            // 782 tiles
    const int NB_L2     = (N_NODESC + 127) / 128;          // 391 tiles

    // ---- layer 1 (TN=64, KC=32, R_N=4; 2 roles) ----
    linear_split_kernel<D_INC, D_HIDC, 64, 32, 0><<<2 * NB_L1, 256>>>(
        x, Wl1, bl1, Wr1, br1, 0);
    gat_node_kernel<D_HIDC, 0><<<GRID_GAT, 256>>>(We1, att1, bias1, out);

    // ---- layer 2 (input = g_h via insel=1; TN=128, KC=32, R_N=4; 2 roles) ----
    linear_split_kernel<D_HIDC, D_OUTC, 128, 32, 1><<<2 * NB_L2, 256>>>(
        x, Wl2, bl2, Wr2, br2, 1);
    gat_node_kernel<D_OUTC, 1><<<GRID_GAT, 256>>>(We2, att2, bias2, out);
}

// round 12
// speedup vs baseline: 1.4644x; 1.4644x over previous
#include <cuda_runtime.h>

#define N_NODESC 50000
#define N_EDGESC 800000
#define E2C (N_EDGESC + N_NODESC)
#define D_INC 128
#define D_HIDC 64
#define D_OUTC 32
#define SCAN_BLK 256
#define SCAN_GRID ((N_NODESC + SCAN_BLK - 1) / SCAN_BLK)   // 196

// ---------------- scratch (device globals; never referenced from host) --------
__device__ __align__(16) int   g_count[N_NODESC];
__device__ __align__(16) float g_attr_sum[N_NODESC];
__device__ __align__(16) float g_loop_attr[N_NODESC];
__device__ __align__(16) int   g_row_ptr[N_NODESC + 1];
__device__ __align__(16) int   g_cursor[N_NODESC];
__device__ __align__(16) int2  g_csr[E2C];                 // (src, attr-bits)
__device__ __align__(16) int   g_bsum[SCAN_GRID];
__device__ __align__(16) int   g_boff[SCAN_GRID];
__device__ __align__(16) float g_xl [N_NODESC * D_HIDC];
__device__ __align__(16) float g_xr [N_NODESC * D_HIDC];
__device__ __align__(16) float g_h  [N_NODESC * D_HIDC];
__device__ __align__(16) float g_xl2[N_NODESC * D_OUTC];
__device__ __align__(16) float g_xr2[N_NODESC * D_OUTC];

__device__ __forceinline__ const float* lin_in_ptr(const float* xparam, int sel) {
    return (sel == 0) ? xparam : g_h;
}

// ---------------- preprocessing (R5-proven multi-block structure) ---------------
__global__ void init_kernel() {
    int i = blockIdx.x * blockDim.x + threadIdx.x;
    if (i < N_NODESC) {
        g_count[i] = 0;
        g_attr_sum[i] = 0.f;
        g_cursor[i] = 0;
    }
}

__global__ void count_kernel(const int* __restrict__ ei,
                             const float* __restrict__ ew) {
    int e = blockIdx.x * blockDim.x + threadIdx.x;
    if (e < N_EDGESC) {
        int d = ei[N_EDGESC + e];
        if ((unsigned)d < (unsigned)N_NODESC) {
            atomicAdd(&g_count[d], 1);
            atomicAdd(&g_attr_sum[d], ew[e]);
        }
    }
}

// ---- multi-block exclusive scan of (count[i]+1) -> row_ptr; also loop_attr ----
__global__ void scan1_kernel() {   // per-block sums + loop_attr
    __shared__ int red[SCAN_BLK];
    int t = threadIdx.x, b = blockIdx.x;
    int i = b * SCAN_BLK + t;
    int val = 0;
    if (i < N_NODESC) {
        int c = g_count[i];
        val = c + 1;
        g_loop_attr[i] = g_attr_sum[i] / fmaxf((float)c, 1.0f);
    }
    red[t] = val;
    __syncthreads();
#pragma unroll
    for (int off = SCAN_BLK / 2; off > 0; off >>= 1) {
        if (t < off) red[t] += red[t + off];
        __syncthreads();
    }
    if (t == 0) g_bsum[b] = red[0];
}

__global__ void scan2_kernel() {   // exclusive scan of 196 block sums
    __shared__ int sh[SCAN_BLK];
    int t = threadIdx.x;
    int orig = (t < SCAN_GRID) ? g_bsum[t] : 0;
    sh[t] = orig;
    __syncthreads();
    for (int off = 1; off < SCAN_BLK; off <<= 1) {
        int v = (t >= off) ? sh[t - off] : 0;
        __syncthreads();
        sh[t] += v;
        __syncthreads();
    }
    if (t < SCAN_GRID) g_boff[t] = sh[t] - orig;
}

__global__ void scan3_kernel() {   // local scan + block offset -> row_ptr
    __shared__ int sh[SCAN_BLK];
    int t = threadIdx.x, b = blockIdx.x;
    int i = b * SCAN_BLK + t;
    int val = (i < N_NODESC) ? (g_count[i] + 1) : 0;
    sh[t] = val;
    __syncthreads();
    for (int off = 1; off < SCAN_BLK; off <<= 1) {
        int v = (t >= off) ? sh[t - off] : 0;
        __syncthreads();
        sh[t] += v;
        __syncthreads();
    }
    if (i < N_NODESC) g_row_ptr[i] = g_boff[b] + sh[t] - val;
    if (i == N_NODESC) g_row_ptr[N_NODESC] = E2C;
}

__global__ void scatter_kernel(const int* __restrict__ ei,
                               const float* __restrict__ ew) {
    int e = blockIdx.x * blockDim.x + threadIdx.x;
    if (e < N_EDGESC) {
        int d = ei[N_EDGESC + e];
        int s = ei[e];
        if ((unsigned)d < (unsigned)N_NODESC && (unsigned)s < (unsigned)N_NODESC) {
            int pos = g_row_ptr[d] + atomicAdd(&g_cursor[d], 1);
            g_csr[pos] = make_int2(s, __float_as_int(ew[e]));
        }
    } else if (e < E2C) {
        int v = e - N_EDGESC;
        int pos = g_row_ptr[v] + atomicAdd(&g_cursor[v], 1);
        g_csr[pos] = make_int2(v, __float_as_int(g_loop_attr[v]));
    }
}

// ---------------- fused linear: yl = x@Wl^T+bl, yr = x@Wr^T+br ------------------
// R10-measured form (62.6us for layer 1): R_N=4, XS=TN+1 odd pitch, scalar x LDS.
template <int DI, int DO, int TN, int KC, int PAIR>
__global__ void __launch_bounds__(256) linear_fused_kernel(
    const float* __restrict__ xparam,
    const float* __restrict__ Wl, const float* __restrict__ bl,
    const float* __restrict__ Wr, const float* __restrict__ br,
    int insel) {
    constexpr int WS   = DO + 4;
    constexpr int XS   = TN + 1;
    constexpr int NT_H = DO / 4;
    constexpr int NT_N = 256 / NT_H;
    constexpr int R_N  = TN / NT_N;
    static_assert(DI % KC == 0 && R_N == 4, "tile config");
    __shared__ __align__(16) float Wls[KC * WS];
    __shared__ __align__(16) float Wrs[KC * WS];
    __shared__ __align__(16) float xs[KC * XS];
    const float* __restrict__ x = lin_in_ptr(xparam, insel);
    float* __restrict__ yl = PAIR ? g_xl2 : g_xl;
    float* __restrict__ yr = PAIR ? g_xr2 : g_xr;
    int t = threadIdx.x;
    int node0 = blockIdx.x * TN;
    int h0 = (t % NT_H) * 4;
    int n0 = (t / NT_H) * R_N;
    float accl[R_N][4], accr[R_N][4];
#pragma unroll
    for (int r = 0; r < R_N; r++)
#pragma unroll
        for (int c = 0; c < 4; c++) { accl[r][c] = 0.f; accr[r][c] = 0.f; }

    for (int c = 0; c < DI / KC; c++) {
        if (c) __syncthreads();
        for (int i = t; i < DO * KC; i += 256) {
            int r = i / KC, k = i % KC;
            Wls[k * WS + r] = Wl[r * DI + c * KC + k];
            Wrs[k * WS + r] = Wr[r * DI + c * KC + k];
        }
        for (int i = t; i < TN * KC; i += 256) {
            int n = i / KC, k = i % KC;
            int nd = node0 + n;
            xs[k * XS + n] = (nd < N_NODESC) ? x[nd * DI + c * KC + k] : 0.f;
        }
        __syncthreads();
#pragma unroll 4
        for (int k = 0; k < KC; k++) {
            float4 wl4 = *reinterpret_cast<const float4*>(&Wls[k * WS + h0]);
            float4 wr4 = *reinterpret_cast<const float4*>(&Wrs[k * WS + h0]);
            float xvr[R_N];
#pragma unroll
            for (int r = 0; r < R_N; r++) xvr[r] = xs[k * XS + n0 + r];
#pragma unroll
            for (int r = 0; r < R_N; r++) {
                accl[r][0] = fmaf(xvr[r], wl4.x, accl[r][0]);
                accl[r][1] = fmaf(xvr[r], wl4.y, accl[r][1]);
                accl[r][2] = fmaf(xvr[r], wl4.z, accl[r][2]);
                accl[r][3] = fmaf(xvr[r], wl4.w, accl[r][3]);
                accr[r][0] = fmaf(xvr[r], wr4.x, accr[r][0]);
                accr[r][1] = fmaf(xvr[r], wr4.y, accr[r][1]);
                accr[r][2] = fmaf(xvr[r], wr4.z, accr[r][2]);
                accr[r][3] = fmaf(xvr[r], wr4.w, accr[r][3]);
            }
        }
    }
#pragma unroll
    for (int r = 0; r < R_N; r++) {
        int node = node0 + n0 + r;
        if (node < N_NODESC) {
            float4 o;
            o.x = accl[r][0] + bl[h0 + 0];
            o.y = accl[r][1] + bl[h0 + 1];
            o.z = accl[r][2] + bl[h0 + 2];
            o.w = accl[r][3] + bl[h0 + 3];
            *reinterpret_cast<float4*>(&yl[node * DO + h0]) = o;
            o.x = accr[r][0] + br[h0 + 0];
            o.y = accr[r][1] + br[h0 + 1];
            o.z = accr[r][2] + br[h0 + 2];
            o.w = accr[r][3] + br[h0 + 3];
            *reinterpret_cast<float4*>(&yr[node * DO + h0]) = o;
        }
    }
}

// ---------------- GATv2 node kernel: warp per node, SINGLE PASS -----------------
// Byte-identical to the R5 champion form.
template <int DH, int LAYER>
__global__ void __launch_bounds__(256) gat_node_kernel(
    const float* __restrict__ We, const float* __restrict__ att,
    const float* __restrict__ bias, float* __restrict__ outp) {
    constexpr int PER = DH / 32;
    const float* __restrict__ xl = (LAYER == 0) ? g_xl : g_xl2;
    const float* __restrict__ xr = (LAYER == 0) ? g_xr : g_xr2;
    float* __restrict__ out = (LAYER == 0) ? g_h : outp;
    int v    = (blockIdx.x * blockDim.x + threadIdx.x) >> 5;
    int lane = threadIdx.x & 31;
    if (v >= N_NODESC) return;

    float xrv[PER], wev[PER], attv[PER], bv[PER];
#pragma unroll
    for (int p = 0; p < PER; p++) {
        int h = lane * PER + p;
        xrv[p]  = xr[v * DH + h];
        wev[p]  = We[h];
        attv[p] = att[h];
        bv[p]   = bias[h];
    }
    int beg = g_row_ptr[v], end = g_row_ptr[v + 1];

    float ssum = 0.f;
    float acc[PER];
#pragma unroll
    for (int p = 0; p < PER; p++) acc[p] = 0.f;

    // software pipeline: edge record + x row prefetched one iteration ahead
    int2 ecur = g_csr[beg];
    float xnext[PER];
    {
        const float* b0 = xl + (size_t)ecur.x * DH + lane * PER;
        if (PER == 2) { float2 t2 = *reinterpret_cast<const float2*>(b0); xnext[0] = t2.x; xnext[1] = t2.y; }
        else          { xnext[0] = *b0; }
    }
    for (int idx = beg; idx < end; idx++) {
        float xls[PER];
#pragma unroll
        for (int p = 0; p < PER; p++) xls[p] = xnext[p];
        float a = __int_as_float(ecur.y);
        int2 enext = (idx + 1 < end) ? g_csr[idx + 1] : ecur;
        const float* bn = xl + (size_t)enext.x * DH + lane * PER;
        if (PER == 2) { float2 t2 = *reinterpret_cast<const float2*>(bn); xnext[0] = t2.x; xnext[1] = t2.y; }
        else          { xnext[0] = *bn; }
        ecur = enext;

        float sc = 0.f;
#pragma unroll
        for (int p = 0; p < PER; p++) {
            float m = xls[p] + xrv[p] + a * wev[p];
            m = m > 0.f ? m : 0.2f * m;
            sc = fmaf(attv[p], m, sc);
        }
#pragma unroll
        for (int o = 16; o; o >>= 1) sc += __shfl_xor_sync(0xffffffffu, sc, o);
        float e = __expf(sc);
        ssum += e;
#pragma unroll
        for (int p = 0; p < PER; p++) acc[p] = fmaf(e, xls[p], acc[p]);
    }
    float inv = 1.f / ssum;
#pragma unroll
    for (int p = 0; p < PER; p++) {
        float o = fmaf(acc[p], inv, bv[p]);
        if (LAYER == 0) {
            o = o > 0.f ? o : (__expf(o) - 1.f);            // elu
        } else {
            o = (o > 20.f ? o : log1pf(__expf(o))) + 1e-4f; // softplus + eps
        }
        out[v * DH + lane * PER + p] = o;
    }
}

// ---------------- launch --------------------------------------------------------
extern "C" void kernel_launch(void* const* d_in, const int* in_sizes, int n_in,
                              void* d_out, int out_size) {
    const float* x     = (const float*)d_in[0];
    const int*   ei    = (const int*)d_in[1];      // edge_index: int32
    const float* ew    = (const float*)d_in[2];
    const float* Wl1   = (const float*)d_in[3];
    const float* bl1   = (const float*)d_in[4];
    const float* Wr1   = (const float*)d_in[5];
    const float* br1   = (const float*)d_in[6];
    const float* We1   = (const float*)d_in[7];
    const float* att1  = (const float*)d_in[8];
    const float* bias1 = (const float*)d_in[9];
    const float* Wl2   = (const float*)d_in[10];
    const float* bl2   = (const float*)d_in[11];
    const float* Wr2   = (const float*)d_in[12];
    const float* br2   = (const float*)d_in[13];
    const float* We2   = (const float*)d_in[14];
    const float* att2  = (const float*)d_in[15];
    const float* bias2 = (const float*)d_in[16];
    float*       out   = (float*)d_out;

    // ---- graph preprocessing / CSR (R5-proven multi-block pipeline) ----
    init_kernel<<<(N_NODESC + 255) / 256, 256>>>();
    count_kernel<<<(N_EDGESC + 255) / 256, 256>>>(ei, ew);
    scan1_kernel<<<SCAN_GRID, SCAN_BLK>>>();
    scan2_kernel<<<1, SCAN_BLK>>>();
    scan3_kernel<<<SCAN_GRID, SCAN_BLK>>>();
    scatter_kernel<<<(E2C + 255) / 256, 256>>>(ei, ew);

    const int GRID_GAT = (N_NODESC * 32 + 255) / 256;   // warp per node

    // ---- layer 1 (TN=64, KC=32, R_N=4) ----
    linear_fused_kernel<D_INC, D_HIDC, 64, 32, 0><<<(N_NODESC + 63) / 64, 256>>>(
        x, Wl1, bl1, Wr1, br1, 0);
    gat_node_kernel<D_HIDC, 0><<<GRID_GAT, 256>>>(We1, att1, bias1, out);

    // ---- layer 2 (input = g_h via insel=1; TN=128, KC=32, R_N=4) ----
    linear_fused_kernel<D_HIDC, D_OUTC, 128, 32, 1><<<(N_NODESC + 127) / 128, 256>>>(
        x, Wl2, bl2, Wr2, br2, 1);
    gat_node_kernel<D_OUTC, 1><<<GRID_GAT, 256>>>(We2, att2, bias2, out);
}

// round 13
// speedup vs baseline: 1.5912x; 1.0866x over previous
#include <cuda_runtime.h>

#define N_NODESC 50000
#define N_EDGESC 800000
#define E2C (N_EDGESC + N_NODESC)
#define D_INC 128
#define D_HIDC 64
#define D_OUTC 32
#define SCAN_BLK 256
#define SCAN_GRID ((N_NODESC + SCAN_BLK - 1) / SCAN_BLK)   // 196

// ---------------- scratch (device globals; never referenced from host) --------
// Zero-initialized at module load; gat layer-0 kernel re-zeros the consumed
// counters each call (measured free in R7/R8) so every replay sees zeros.
__device__ __align__(16) int   g_count[N_NODESC];
__device__ __align__(16) float g_attr_sum[N_NODESC];
__device__ __align__(16) float g_loop_attr[N_NODESC];
__device__ __align__(16) int   g_row_ptr[N_NODESC + 1];
__device__ __align__(16) int   g_cursor[N_NODESC];
__device__ __align__(16) int2  g_csr[E2C];                 // (src, attr-bits)
__device__ __align__(16) int   g_bsum[SCAN_GRID];
__device__ __align__(16) int   g_boff[SCAN_GRID];
__device__ __align__(16) float g_xl [N_NODESC * D_HIDC];
__device__ __align__(16) float g_xr [N_NODESC * D_HIDC];
__device__ __align__(16) float g_h  [N_NODESC * D_HIDC];
__device__ __align__(16) float g_xl2[N_NODESC * D_OUTC];
__device__ __align__(16) float g_xr2[N_NODESC * D_OUTC];

__device__ __forceinline__ const float* lin_in_ptr(const float* xparam, int sel) {
    return (sel == 0) ? xparam : g_h;
}

// ---------------- preprocessing (R5/R12-proven multi-block structure) -----------
__global__ void count_kernel(const int* __restrict__ ei,
                             const float* __restrict__ ew) {
    int e = blockIdx.x * blockDim.x + threadIdx.x;
    if (e < N_EDGESC) {
        int d = ei[N_EDGESC + e];
        if ((unsigned)d < (unsigned)N_NODESC) {
            atomicAdd(&g_count[d], 1);
            atomicAdd(&g_attr_sum[d], ew[e]);
        }
    }
}

__global__ void scan1_kernel() {   // per-block sums + loop_attr
    __shared__ int red[SCAN_BLK];
    int t = threadIdx.x, b = blockIdx.x;
    int i = b * SCAN_BLK + t;
    int val = 0;
    if (i < N_NODESC) {
        int c = g_count[i];
        val = c + 1;
        g_loop_attr[i] = g_attr_sum[i] / fmaxf((float)c, 1.0f);
    }
    red[t] = val;
    __syncthreads();
#pragma unroll
    for (int off = SCAN_BLK / 2; off > 0; off >>= 1) {
        if (t < off) red[t] += red[t + off];
        __syncthreads();
    }
    if (t == 0) g_bsum[b] = red[0];
}

__global__ void scan2_kernel() {   // exclusive scan of 196 block sums
    __shared__ int sh[SCAN_BLK];
    int t = threadIdx.x;
    int orig = (t < SCAN_GRID) ? g_bsum[t] : 0;
    sh[t] = orig;
    __syncthreads();
    for (int off = 1; off < SCAN_BLK; off <<= 1) {
        int v = (t >= off) ? sh[t - off] : 0;
        __syncthreads();
        sh[t] += v;
        __syncthreads();
    }
    if (t < SCAN_GRID) g_boff[t] = sh[t] - orig;
}

__global__ void scan3_kernel() {   // local scan + block offset -> row_ptr
    __shared__ int sh[SCAN_BLK];
    int t = threadIdx.x, b = blockIdx.x;
    int i = b * SCAN_BLK + t;
    int val = (i < N_NODESC) ? (g_count[i] + 1) : 0;
    sh[t] = val;
    __syncthreads();
    for (int off = 1; off < SCAN_BLK; off <<= 1) {
        int v = (t >= off) ? sh[t - off] : 0;
        __syncthreads();
        sh[t] += v;
        __syncthreads();
    }
    if (i < N_NODESC) g_row_ptr[i] = g_boff[b] + sh[t] - val;
    if (i == N_NODESC) g_row_ptr[N_NODESC] = E2C;
}

__global__ void scatter_kernel(const int* __restrict__ ei,
                               const float* __restrict__ ew) {
    int e = blockIdx.x * blockDim.x + threadIdx.x;
    if (e < N_EDGESC) {
        int d = ei[N_EDGESC + e];
        int s = ei[e];
        if ((unsigned)d < (unsigned)N_NODESC && (unsigned)s < (unsigned)N_NODESC) {
            int pos = g_row_ptr[d] + atomicAdd(&g_cursor[d], 1);
            g_csr[pos] = make_int2(s, __float_as_int(ew[e]));
        }
    } else if (e < E2C) {
        int v = e - N_EDGESC;
        int pos = g_row_ptr[v] + atomicAdd(&g_cursor[v], 1);
        g_csr[pos] = make_int2(v, __float_as_int(g_loop_attr[v]));
    }
}

// ---------------- fused linear: yl = x@Wl^T+bl, yr = x@Wr^T+br ------------------
// R10/R12-measured form (62.6us layer 1): R_N=4, XS=TN+1 odd pitch, scalar x LDS.
template <int DI, int DO, int TN, int KC, int PAIR>
__global__ void __launch_bounds__(256) linear_fused_kernel(
    const float* __restrict__ xparam,
    const float* __restrict__ Wl, const float* __restrict__ bl,
    const float* __restrict__ Wr, const float* __restrict__ br,
    int insel) {
    constexpr int WS   = DO + 4;
    constexpr int XS   = TN + 1;
    constexpr int NT_H = DO / 4;
    constexpr int NT_N = 256 / NT_H;
    constexpr int R_N  = TN / NT_N;
    static_assert(DI % KC == 0 && R_N == 4, "tile config");
    __shared__ __align__(16) float Wls[KC * WS];
    __shared__ __align__(16) float Wrs[KC * WS];
    __shared__ __align__(16) float xs[KC * XS];
    const float* __restrict__ x = lin_in_ptr(xparam, insel);
    float* __restrict__ yl = PAIR ? g_xl2 : g_xl;
    float* __restrict__ yr = PAIR ? g_xr2 : g_xr;
    int t = threadIdx.x;
    int node0 = blockIdx.x * TN;
    int h0 = (t % NT_H) * 4;
    int n0 = (t / NT_H) * R_N;
    float accl[R_N][4], accr[R_N][4];
#pragma unroll
    for (int r = 0; r < R_N; r++)
#pragma unroll
        for (int c = 0; c < 4; c++) { accl[r][c] = 0.f; accr[r][c] = 0.f; }

    for (int c = 0; c < DI / KC; c++) {
        if (c) __syncthreads();
        for (int i = t; i < DO * KC; i += 256) {
            int r = i / KC, k = i % KC;
            Wls[k * WS + r] = Wl[r * DI + c * KC + k];
            Wrs[k * WS + r] = Wr[r * DI + c * KC + k];
        }
        for (int i = t; i < TN * KC; i += 256) {
            int n = i / KC, k = i % KC;
            int nd = node0 + n;
            xs[k * XS + n] = (nd < N_NODESC) ? x[nd * DI + c * KC + k] : 0.f;
        }
        __syncthreads();
#pragma unroll 4
        for (int k = 0; k < KC; k++) {
            float4 wl4 = *reinterpret_cast<const float4*>(&Wls[k * WS + h0]);
            float4 wr4 = *reinterpret_cast<const float4*>(&Wrs[k * WS + h0]);
            float xvr[R_N];
#pragma unroll
            for (int r = 0; r < R_N; r++) xvr[r] = xs[k * XS + n0 + r];
#pragma unroll
            for (int r = 0; r < R_N; r++) {
                accl[r][0] = fmaf(xvr[r], wl4.x, accl[r][0]);
                accl[r][1] = fmaf(xvr[r], wl4.y, accl[r][1]);
                accl[r][2] = fmaf(xvr[r], wl4.z, accl[r][2]);
                accl[r][3] = fmaf(xvr[r], wl4.w, accl[r][3]);
                accr[r][0] = fmaf(xvr[r], wr4.x, accr[r][0]);
                accr[r][1] = fmaf(xvr[r], wr4.y, accr[r][1]);
                accr[r][2] = fmaf(xvr[r], wr4.z, accr[r][2]);
                accr[r][3] = fmaf(xvr[r], wr4.w, accr[r][3]);
            }
        }
    }
#pragma unroll
    for (int r = 0; r < R_N; r++) {
        int node = node0 + n0 + r;
        if (node < N_NODESC) {
            float4 o;
            o.x = accl[r][0] + bl[h0 + 0];
            o.y = accl[r][1] + bl[h0 + 1];
            o.z = accl[r][2] + bl[h0 + 2];
            o.w = accl[r][3] + bl[h0 + 3];
            *reinterpret_cast<float4*>(&yl[node * DO + h0]) = o;
            o.x = accr[r][0] + br[h0 + 0];
            o.y = accr[r][1] + br[h0 + 1];
            o.z = accr[r][2] + br[h0 + 2];
            o.w = accr[r][3] + br[h0 + 3];
            *reinterpret_cast<float4*>(&yr[node * DO + h0]) = o;
        }
    }
}

// ---------------- GATv2 node kernel: warp per node, 2-edge ILP ------------------
// Warp-per-node single pass (R5 structure), processing TWO edges per iteration:
// loop overhead amortizes, the two gathers issue back-to-back (MLP=2), and the
// two shuffle-reduction chains interleave to hide SHFL latency.
// LAYER 0 additionally re-zeros the preprocessing counters for the next replay.
template <int DH, int LAYER>
__global__ void __launch_bounds__(256) gat_node_kernel(
    const float* __restrict__ We, const float* __restrict__ att,
    const float* __restrict__ bias, float* __restrict__ outp) {
    constexpr int PER = DH / 32;
    const float* __restrict__ xl = (LAYER == 0) ? g_xl : g_xl2;
    const float* __restrict__ xr = (LAYER == 0) ? g_xr : g_xr2;
    float* __restrict__ out = (LAYER == 0) ? g_h : outp;
    int gi = blockIdx.x * blockDim.x + threadIdx.x;
    if (LAYER == 0 && gi < N_NODESC) {           // restore zero-invariant
        g_count[gi] = 0;
        g_attr_sum[gi] = 0.f;
        g_cursor[gi] = 0;
    }
    int v    = gi >> 5;
    int lane = gi & 31;
    if (v >= N_NODESC) return;

    float xrv[PER], wev[PER], attv[PER], bv[PER];
#pragma unroll
    for (int p = 0; p < PER; p++) {
        int h = lane * PER + p;
        xrv[p]  = xr[v * DH + h];
        wev[p]  = We[h];
        attv[p] = att[h];
        bv[p]   = bias[h];
    }
    int beg = g_row_ptr[v], end = g_row_ptr[v + 1];   // end > beg (self loop)

    float ssum = 0.f;
    float acc[PER];
#pragma unroll
    for (int p = 0; p < PER; p++) acc[p] = 0.f;

    int idx = beg;
    for (; idx + 1 < end; idx += 2) {
        int2 e0 = g_csr[idx];
        int2 e1 = g_csr[idx + 1];
        const float* p0 = xl + (size_t)e0.x * DH + lane * PER;
        const float* p1 = xl + (size_t)e1.x * DH + lane * PER;
        float x0[PER], x1[PER];
        if (PER == 2) {
            float2 t0 = *reinterpret_cast<const float2*>(p0);
            float2 t1 = *reinterpret_cast<const float2*>(p1);
            x0[0] = t0.x; x0[1] = t0.y;
            x1[0] = t1.x; x1[1] = t1.y;
        } else {
            x0[0] = *p0; x1[0] = *p1;
        }
        float a0 = __int_as_float(e0.y);
        float a1 = __int_as_float(e1.y);
        float sc0 = 0.f, sc1 = 0.f;
#pragma unroll
        for (int p = 0; p < PER; p++) {
            float m0 = x0[p] + xrv[p] + a0 * wev[p];
            float m1 = x1[p] + xrv[p] + a1 * wev[p];
            m0 = m0 > 0.f ? m0 : 0.2f * m0;
            m1 = m1 > 0.f ? m1 : 0.2f * m1;
            sc0 = fmaf(attv[p], m0, sc0);
            sc1 = fmaf(attv[p], m1, sc1);
        }
#pragma unroll
        for (int o = 16; o; o >>= 1) {
            sc0 += __shfl_xor_sync(0xffffffffu, sc0, o);
            sc1 += __shfl_xor_sync(0xffffffffu, sc1, o);
        }
        float ex0 = __expf(sc0);
        float ex1 = __expf(sc1);
        ssum += ex0 + ex1;
#pragma unroll
        for (int p = 0; p < PER; p++) {
            acc[p] = fmaf(ex0, x0[p], acc[p]);
            acc[p] = fmaf(ex1, x1[p], acc[p]);
        }
    }
    if (idx < end) {                       // odd tail
        int2 e0 = g_csr[idx];
        const float* p0 = xl + (size_t)e0.x * DH + lane * PER;
        float x0[PER];
        if (PER == 2) {
            float2 t0 = *reinterpret_cast<const float2*>(p0);
            x0[0] = t0.x; x0[1] = t0.y;
        } else {
            x0[0] = *p0;
        }
        float a0 = __int_as_float(e0.y);
        float sc0 = 0.f;
#pragma unroll
        for (int p = 0; p < PER; p++) {
            float m0 = x0[p] + xrv[p] + a0 * wev[p];
            m0 = m0 > 0.f ? m0 : 0.2f * m0;
            sc0 = fmaf(attv[p], m0, sc0);
        }
#pragma unroll
        for (int o = 16; o; o >>= 1) sc0 += __shfl_xor_sync(0xffffffffu, sc0, o);
        float ex0 = __expf(sc0);
        ssum += ex0;
#pragma unroll
        for (int p = 0; p < PER; p++) acc[p] = fmaf(ex0, x0[p], acc[p]);
    }

    float inv = 1.f / ssum;
#pragma unroll
    for (int p = 0; p < PER; p++) {
        float o = fmaf(acc[p], inv, bv[p]);
        if (LAYER == 0) {
            o = o > 0.f ? o : (__expf(o) - 1.f);            // elu
        } else {
            o = (o > 20.f ? o : log1pf(__expf(o))) + 1e-4f; // softplus + eps
        }
        out[v * DH + lane * PER + p] = o;
    }
}

// ---------------- launch --------------------------------------------------------
extern "C" void kernel_launch(void* const* d_in, const int* in_sizes, int n_in,
                              void* d_out, int out_size) {
    const float* x     = (const float*)d_in[0];
    const int*   ei    = (const int*)d_in[1];      // edge_index: int32
    const float* ew    = (const float*)d_in[2];
    const float* Wl1   = (const float*)d_in[3];
    const float* bl1   = (const float*)d_in[4];
    const float* Wr1   = (const float*)d_in[5];
    const float* br1   = (const float*)d_in[6];
    const float* We1   = (const float*)d_in[7];
    const float* att1  = (const float*)d_in[8];
    const float* bias1 = (const float*)d_in[9];
    const float* Wl2   = (const float*)d_in[10];
    const float* bl2   = (const float*)d_in[11];
    const float* Wr2   = (const float*)d_in[12];
    const float* br2   = (const float*)d_in[13];
    const float* We2   = (const float*)d_in[14];
    const float* att2  = (const float*)d_in[15];
    const float* bias2 = (const float*)d_in[16];
    float*       out   = (float*)d_out;

    // ---- graph preprocessing / CSR (counters zero by invariant) ----
    count_kernel<<<(N_EDGESC + 255) / 256, 256>>>(ei, ew);
    scan1_kernel<<<SCAN_GRID, SCAN_BLK>>>();
    scan2_kernel<<<1, SCAN_BLK>>>();
    scan3_kernel<<<SCAN_GRID, SCAN_BLK>>>();
    scatter_kernel<<<(E2C + 255) / 256, 256>>>(ei, ew);

    const int GRID_GAT = (N_NODESC * 32 + 255) / 256;   // warp per node

    // ---- layer 1 (TN=64, KC=32, R_N=4) ----
    linear_fused_kernel<D_INC, D_HIDC, 64, 32, 0><<<(N_NODESC + 63) / 64, 256>>>(
        x, Wl1, bl1, Wr1, br1, 0);
    gat_node_kernel<D_HIDC, 0><<<GRID_GAT, 256>>>(We1, att1, bias1, out);

    // ---- layer 2 (input = g_h via insel=1; TN=128, KC=32, R_N=4) ----
    linear_fused_kernel<D_HIDC, D_OUTC, 128, 32, 1><<<(N_NODESC + 127) / 128, 256>>>(
        x, Wl2, bl2, Wr2, br2, 1);
    gat_node_kernel<D_OUTC, 1><<<GRID_GAT, 256>>>(We2, att2, bias2, out);
}